// round 10
// baseline (speedup 1.0000x reference)
#include <cuda_runtime.h>
#include <cuda_fp16.h>
#include <cstdint>

#define HEADS   8
#define DK      64
#define DV      192
#define BATCH   4
#define SEQ     1536
#define DMODEL  1536
#define MROWS   (BATCH*SEQ)          // 6144
#define NQK     (HEADS*DK)           // 512
#define NV      (HEADS*DV)           // 1536

// ------------------------- global scratch (no allocs) -----------------------
__device__ __half g_Xh[MROWS * DMODEL], g_Xl[MROWS * DMODEL];   // X hi/lo fp16
__device__ __half g_Wq[DMODEL * NQK];                            // W single fp16
__device__ __half g_Wk[DMODEL * NQK];
__device__ __half g_Wv[DMODEL * NV];
__device__ __half g_Q [MROWS * NQK];                             // Q single fp16 (pre-scaled)
__device__ __half g_Kh[MROWS * NQK], g_Kl[MROWS * NQK];          // K hi/lo fp16
__device__ __half g_V [MROWS * NV];                              // V single fp16

// ------------------------------- helpers ------------------------------------
__device__ __forceinline__ unsigned s2u(const void* p) {
    return (unsigned)__cvta_generic_to_shared(p);
}
__device__ __forceinline__ unsigned packh2(float a, float b) {
    __half ha = __float2half_rn(a), hb = __float2half_rn(b);
    return (unsigned)__half_as_ushort(ha) | ((unsigned)__half_as_ushort(hb) << 16);
}
__device__ __forceinline__ void split2h(float x, float y, unsigned& h, unsigned& l) {
    __half hx = __float2half_rn(x), hy = __float2half_rn(y);
    __half lx = __float2half_rn(x - __half2float(hx));
    __half ly = __float2half_rn(y - __half2float(hy));
    h = (unsigned)__half_as_ushort(hx) | ((unsigned)__half_as_ushort(hy) << 16);
    l = (unsigned)__half_as_ushort(lx) | ((unsigned)__half_as_ushort(ly) << 16);
}
__device__ __forceinline__ void ldm_x4(unsigned* r, unsigned a) {
    asm volatile("ldmatrix.sync.aligned.m8n8.x4.shared.b16 {%0,%1,%2,%3}, [%4];"
        : "=r"(r[0]), "=r"(r[1]), "=r"(r[2]), "=r"(r[3]) : "r"(a));
}
__device__ __forceinline__ void ldm_x4_t(unsigned* r, unsigned a) {
    asm volatile("ldmatrix.sync.aligned.m8n8.x4.trans.shared.b16 {%0,%1,%2,%3}, [%4];"
        : "=r"(r[0]), "=r"(r[1]), "=r"(r[2]), "=r"(r[3]) : "r"(a));
}
__device__ __forceinline__ void mma_f16(float* d, const unsigned* a, const unsigned* b) {
    asm volatile(
        "mma.sync.aligned.m16n8k16.row.col.f32.f16.f16.f32 "
        "{%0,%1,%2,%3}, {%4,%5,%6,%7}, {%8,%9}, {%0,%1,%2,%3};\n"
        : "+f"(d[0]), "+f"(d[1]), "+f"(d[2]), "+f"(d[3])
        : "r"(a[0]), "r"(a[1]), "r"(a[2]), "r"(a[3]), "r"(b[0]), "r"(b[1]));
}
__device__ __forceinline__ void cp16(void* dst, const void* src) {
    unsigned d = s2u(dst);
    asm volatile("cp.async.ca.shared.global [%0], [%1], 16;\n" :: "r"(d), "l"(src));
}
__device__ __forceinline__ void cp_commit() { asm volatile("cp.async.commit_group;\n"); }
__device__ __forceinline__ void cp_wait0()  { asm volatile("cp.async.wait_group 0;\n" ::: "memory"); }
__device__ __forceinline__ void cp_wait1()  { asm volatile("cp.async.wait_group 1;\n" ::: "memory"); }

// --------------------- fp32 -> fp16 hi/lo split (X) --------------------------
__global__ void convert_split_h(const float4* __restrict__ in,
                                uint2* __restrict__ oh, uint2* __restrict__ ol, int n4)
{
    int i = blockIdx.x * blockDim.x + threadIdx.x;
    if (i >= n4) return;
    float4 v = in[i];
    uint2 H, L;
    split2h(v.x, v.y, H.x, L.x);
    split2h(v.z, v.w, H.y, L.y);
    oh[i] = H;  ol[i] = L;
}
// ----------- fp32 -> fp16 single convert, all three W in one launch ----------
#define NQK4 (DMODEL * NQK / 4)   // 196608
#define NV4  (DMODEL * NV / 4)    // 589824
__global__ void convert_w_all(const float4* __restrict__ wq, const float4* __restrict__ wk,
                              const float4* __restrict__ wv,
                              uint2* __restrict__ oq, uint2* __restrict__ ok,
                              uint2* __restrict__ ov)
{
    int i = blockIdx.x * blockDim.x + threadIdx.x;
    const float4* in;  uint2* o;  int j;
    if (i < NQK4)               { in = wq; o = oq; j = i; }
    else if (i < 2 * NQK4)      { in = wk; o = ok; j = i - NQK4; }
    else if (i < 2 * NQK4 + NV4){ in = wv; o = ov; j = i - 2 * NQK4; }
    else return;
    float4 v = in[j];
    uint2 H;
    H.x = packh2(v.x, v.y);
    H.y = packh2(v.z, v.w);
    o[j] = H;
}

// ---------------------------------------------------------------------------
// Fused projection GEMM (fp16) — per-batch slice (bm0 = batch * 12).
// Q,K: 2-product (Xh+Xl)@W.  V: 1-product Xh@W.
// Segments by bn: <4 -> Q ; <8 -> K ; else -> V.
// BM=128 BN=128 BK=32, 256 thr, warp tile 32x64, cp.async 3-stage.
// ---------------------------------------------------------------------------
#define GEMM_STAGE_ELEMS 14592
#define GEMM_SMEM_BYTES  (3 * GEMM_STAGE_ELEMS * 2)   // 87552

__global__ __launch_bounds__(256, 2)
void gemm_fused(const __half* __restrict__ Ahg, const __half* __restrict__ Alg,
                const __half* __restrict__ Wq_, const __half* __restrict__ Wk_,
                const __half* __restrict__ Wv_,
                __half* __restrict__ Q_, __half* __restrict__ Kh_,
                __half* __restrict__ Kl_, __half* __restrict__ V_, int bm0)
{
    extern __shared__ __half smg[];
    const int tid = threadIdx.x, lane = tid & 31, wid = tid >> 5;
    const int g = lane >> 2, tg = lane & 3;
    const int wm = (wid >> 1) * 32, wn = (wid & 1) * 64;
    const int bm = bm0 + blockIdx.y, bn_g = blockIdx.x;
    const int K = DMODEL;
    const int NT = K >> 5;   // 48

    const __half* Bg;
    int Nb, bnn, seg;
    if (bn_g < 4)      { Bg = Wq_; Nb = NQK; bnn = bn_g;     seg = 0; }
    else if (bn_g < 8) { Bg = Wk_; Nb = NQK; bnn = bn_g - 4; seg = 1; }
    else               { Bg = Wv_; Nb = NV;  bnn = bn_g - 8; seg = 2; }
    const float alpha = (seg == 0) ? 0.125f : 1.0f;
    const bool use_lo = (seg != 2);     // V: single product

    float d[2][8][4];
#pragma unroll
    for (int mt = 0; mt < 2; mt++)
#pragma unroll
        for (int nt = 0; nt < 8; nt++)
#pragma unroll
            for (int i = 0; i < 4; i++) d[mt][nt][i] = 0.f;

    auto issue = [&](int it) {
        __half* s = smg + (it % 3) * GEMM_STAGE_ELEMS;
        int k0 = it * 32;
#pragma unroll
        for (int j = 0; j < 2; j++) {
            int c = tid + j * 256;
            int ar = c >> 2, ac = (c & 3) << 3;
            size_t ga = (size_t)(bm * 128 + ar) * K + k0 + ac;
            cp16(s + ar * 40 + ac, Ahg + ga);
            if (use_lo) cp16(s + 5120 + ar * 40 + ac, Alg + ga);
            int br = c >> 4, bc = (c & 15) << 3;
            size_t gb = (size_t)(k0 + br) * Nb + bnn * 128 + bc;
            cp16(s + 10240 + br * 136 + bc, Bg + gb);
        }
        cp_commit();
    };

    issue(0);
    issue(1);
    for (int it = 0; it < NT; it++) {
        if (it + 1 < NT) cp_wait1(); else cp_wait0();
        __syncthreads();
        if (it + 2 < NT) issue(it + 2);
        const __half* s = smg + (it % 3) * GEMM_STAGE_ELEMS;

#pragma unroll
        for (int ks = 0; ks < 2; ks++) {
            const int kk = ks * 16;
            unsigned ah[2][4], al[2][4];
            const int arow = lane & 15, acol = kk + ((lane >> 4) << 3);
#pragma unroll
            for (int mt = 0; mt < 2; mt++) {
                ldm_x4(ah[mt], s2u(s + (wm + mt * 16 + arow) * 40 + acol));
                if (use_lo)
                    ldm_x4(al[mt], s2u(s + 5120 + (wm + mt * 16 + arow) * 40 + acol));
            }
            const int krow = kk + (lane & 7) + ((lane >> 3) & 1) * 8;
#pragma unroll
            for (int ntp = 0; ntp < 4; ntp++) {
                const int ncol = wn + ntp * 16 + ((lane >> 4) << 3);
                unsigned bh[4];
                ldm_x4_t(bh, s2u(s + 10240 + krow * 136 + ncol));
#pragma unroll
                for (int mt = 0; mt < 2; mt++) {
                    mma_f16(d[mt][2 * ntp],     ah[mt], bh);
                    mma_f16(d[mt][2 * ntp + 1], ah[mt], bh + 2);
                    if (use_lo) {
                        mma_f16(d[mt][2 * ntp],     al[mt], bh);
                        mma_f16(d[mt][2 * ntp + 1], al[mt], bh + 2);
                    }
                }
            }
        }
    }

    // epilogue (per segment)
#pragma unroll
    for (int mt = 0; mt < 2; mt++) {
        int r0 = bm * 128 + wm + mt * 16 + g;
#pragma unroll
        for (int nt = 0; nt < 8; nt++) {
            int c = bnn * 128 + wn + nt * 8 + 2 * tg;
            float v0 = d[mt][nt][0] * alpha, v1 = d[mt][nt][1] * alpha;
            float v2 = d[mt][nt][2] * alpha, v3 = d[mt][nt][3] * alpha;
            if (seg == 0) {
                *(unsigned*)(Q_ + (size_t)r0 * NQK + c)       = packh2(v0, v1);
                *(unsigned*)(Q_ + (size_t)(r0 + 8) * NQK + c) = packh2(v2, v3);
            } else if (seg == 1) {
                unsigned h01, l01, h23, l23;
                split2h(v0, v1, h01, l01);
                split2h(v2, v3, h23, l23);
                *(unsigned*)(Kh_ + (size_t)r0 * NQK + c)       = h01;
                *(unsigned*)(Kl_ + (size_t)r0 * NQK + c)       = l01;
                *(unsigned*)(Kh_ + (size_t)(r0 + 8) * NQK + c) = h23;
                *(unsigned*)(Kl_ + (size_t)(r0 + 8) * NQK + c) = l23;
            } else {
                *(unsigned*)(V_ + (size_t)r0 * NV + c)       = packh2(v0, v1);
                *(unsigned*)(V_ + (size_t)(r0 + 8) * NV + c) = packh2(v2, v3);
            }
        }
    }
}

// ---------------------------------------------------------------------------
// Flash attention (fp16) — per-batch (b passed as arg; grid = (12, HEADS)).
// Arithmetic identical to round 9 (bit-identical results).
// ---------------------------------------------------------------------------
#define FLASH_STAGE_BYTES 44032
#define FLASH_SMEM_BYTES  (18432 + 3 * FLASH_STAGE_BYTES)   // 150528

__global__ __launch_bounds__(256, 1)
void flash_tc(const __half* __restrict__ Qg, const __half* __restrict__ Khg,
              const __half* __restrict__ Klg, const __half* __restrict__ V,
              float* __restrict__ out, int b)
{
    extern __shared__ char smc[];
    __half* Qs = (__half*)smc;                     // [128][72]

    const int tid = threadIdx.x, lane = tid & 31, wid = tid >> 5;
    const int g = lane >> 2, tg = lane & 3;
    const int w16 = wid * 16;
    const int h = blockIdx.y;
    const int q0 = blockIdx.x * 128;
    const int NT = SEQ / 64;   // 24

#pragma unroll
    for (int r = 0; r < 4; r++) {
        int idx = tid + r * 256;
        int qr = idx >> 3, kc = (idx & 7) << 3;
        *(uint4*)(Qs + qr * 72 + kc) =
            *(const uint4*)(Qg + (size_t)(b * SEQ + q0 + qr) * NQK + h * DK + kc);
    }

    auto issue_kv = [&](int kt) {
        char* st = smc + 18432 + (kt % 3) * FLASH_STAGE_BYTES;
        const int kv0 = kt * 64;
#pragma unroll
        for (int i = 0; i < 2; i++) {
            int idx = tid + i * 256;
            int r = idx >> 3, q = idx & 7;
            size_t go = (size_t)(b * SEQ + kv0 + r) * NQK + h * DK + q * 8;
            cp16(st + r * 144 + q * 16, Khg + go);
            cp16(st + 9216 + r * 144 + q * 16, Klg + go);
        }
#pragma unroll
        for (int i = 0; i < 6; i++) {
            int idx = tid + i * 256;
            int r = idx / 24, cq = idx % 24;
            cp16(st + 18432 + r * 400 + cq * 16,
                 V + (size_t)(b * SEQ + kv0 + r) * NV + h * DV + cq * 8);
        }
        cp_commit();
    };

    issue_kv(0);
    issue_kv(1);
    __syncthreads();

    unsigned qf[4][4];
#pragma unroll
    for (int ks = 0; ks < 4; ks++) {
        const int arow = lane & 15, acol = ks * 16 + ((lane >> 4) << 3);
        ldm_x4(qf[ks], s2u(Qs + (w16 + arow) * 72 + acol));
    }

    float m0 = -1e30f, m1 = -1e30f, l0s = 0.f, l1s = 0.f;
    float o[24][4];
#pragma unroll
    for (int nt = 0; nt < 24; nt++)
#pragma unroll
        for (int i = 0; i < 4; i++) o[nt][i] = 0.f;

    for (int kt = 0; kt < NT; kt++) {
        if (kt + 1 < NT) cp_wait1(); else cp_wait0();
        __syncthreads();
        if (kt + 2 < NT) issue_kv(kt + 2);

        char* st = smc + 18432 + (kt % 3) * FLASH_STAGE_BYTES;
        __half* Kh_s = (__half*)st;
        __half* Kl_s = (__half*)(st + 9216);
        __half* Vs   = (__half*)(st + 18432);

        float s[8][4];
#pragma unroll
        for (int nt = 0; nt < 8; nt++)
#pragma unroll
            for (int i = 0; i < 4; i++) s[nt][i] = 0.f;

#pragma unroll
        for (int ks = 0; ks < 4; ks++) {
            const int kk = ks * 16;
            const int nrow = ((lane >> 4) << 3) + (lane & 7);
            const int kcol = kk + ((lane >> 3) & 1) * 8;
#pragma unroll
            for (int ntp = 0; ntp < 4; ntp++) {
                unsigned kh[4], kl[4];
                ldm_x4(kh, s2u(Kh_s + (ntp * 16 + nrow) * 72 + kcol));
                ldm_x4(kl, s2u(Kl_s + (ntp * 16 + nrow) * 72 + kcol));
                mma_f16(s[2 * ntp],     qf[ks], kh);
                mma_f16(s[2 * ntp],     qf[ks], kl);
                mma_f16(s[2 * ntp + 1], qf[ks], kh + 2);
                mma_f16(s[2 * ntp + 1], qf[ks], kl + 2);
            }
        }

        float mx0 = -1e30f, mx1 = -1e30f;
#pragma unroll
        for (int nt = 0; nt < 8; nt++) {
            mx0 = fmaxf(mx0, fmaxf(s[nt][0], s[nt][1]));
            mx1 = fmaxf(mx1, fmaxf(s[nt][2], s[nt][3]));
        }
        mx0 = fmaxf(mx0, __shfl_xor_sync(0xffffffffu, mx0, 1));
        mx0 = fmaxf(mx0, __shfl_xor_sync(0xffffffffu, mx0, 2));
        mx1 = fmaxf(mx1, __shfl_xor_sync(0xffffffffu, mx1, 1));
        mx1 = fmaxf(mx1, __shfl_xor_sync(0xffffffffu, mx1, 2));

        float nm0 = fmaxf(m0, mx0), nm1 = fmaxf(m1, mx1);
        float a0 = __expf(m0 - nm0), a1 = __expf(m1 - nm1);
        float sum0 = 0.f, sum1 = 0.f;
#pragma unroll
        for (int nt = 0; nt < 8; nt++) {
            s[nt][0] = __expf(s[nt][0] - nm0); sum0 += s[nt][0];
            s[nt][1] = __expf(s[nt][1] - nm0); sum0 += s[nt][1];
            s[nt][2] = __expf(s[nt][2] - nm1); sum1 += s[nt][2];
            s[nt][3] = __expf(s[nt][3] - nm1); sum1 += s[nt][3];
        }
        sum0 += __shfl_xor_sync(0xffffffffu, sum0, 1);
        sum0 += __shfl_xor_sync(0xffffffffu, sum0, 2);
        sum1 += __shfl_xor_sync(0xffffffffu, sum1, 1);
        sum1 += __shfl_xor_sync(0xffffffffu, sum1, 2);
        l0s = l0s * a0 + sum0;  l1s = l1s * a1 + sum1;
        m0 = nm0;  m1 = nm1;

#pragma unroll
        for (int nt = 0; nt < 24; nt++) {
            o[nt][0] *= a0; o[nt][1] *= a0;
            o[nt][2] *= a1; o[nt][3] *= a1;
        }

#pragma unroll
        for (int c = 0; c < 4; c++) {
            unsigned ap[4];
            ap[0] = packh2(s[2 * c][0],     s[2 * c][1]);
            ap[1] = packh2(s[2 * c][2],     s[2 * c][3]);
            ap[2] = packh2(s[2 * c + 1][0], s[2 * c + 1][1]);
            ap[3] = packh2(s[2 * c + 1][2], s[2 * c + 1][3]);
            const int krow = 16 * c + (lane & 7) + ((lane >> 3) & 1) * 8;
#pragma unroll
            for (int ntp = 0; ntp < 12; ntp++) {
                const int ncol = ntp * 16 + ((lane >> 4) << 3);
                unsigned bv[4];
                ldm_x4_t(bv, s2u(Vs + krow * 200 + ncol));
                mma_f16(o[2 * ntp],     ap, bv);
                mma_f16(o[2 * ntp + 1], ap, bv + 2);
            }
        }
    }

    float i0 = 1.f / l0s, i1 = 1.f / l1s;
    int r0 = b * SEQ + q0 + w16 + g, r1 = r0 + 8;
#pragma unroll
    for (int nt = 0; nt < 24; nt++) {
        int c = h * DV + nt * 8 + 2 * tg;
        *(float2*)(out + (size_t)r0 * NV + c) = make_float2(o[nt][0] * i0, o[nt][1] * i0);
        *(float2*)(out + (size_t)r1 * NV + c) = make_float2(o[nt][2] * i1, o[nt][3] * i1);
    }
}

// ---------------------------------------------------------------------------
extern "C" void kernel_launch(void* const* d_in, const int* in_sizes, int n_in,
                              void* d_out, int out_size)
{
    const float* X  = (const float*)d_in[0];
    const float* Wq = (const float*)d_in[1];
    const float* Wk = (const float*)d_in[2];
    const float* Wv = (const float*)d_in[3];
    float* out = (float*)d_out;

    void *xh, *xl, *wq, *wk, *wv, *q, *kh, *kl, *pv;
    cudaGetSymbolAddress(&xh, g_Xh); cudaGetSymbolAddress(&xl, g_Xl);
    cudaGetSymbolAddress(&wq, g_Wq); cudaGetSymbolAddress(&wk, g_Wk);
    cudaGetSymbolAddress(&wv, g_Wv);
    cudaGetSymbolAddress(&q, g_Q);
    cudaGetSymbolAddress(&kh, g_Kh); cudaGetSymbolAddress(&kl, g_Kl);
    cudaGetSymbolAddress(&pv, g_V);

    static cudaStream_t s1 = nullptr;
    static cudaEvent_t evG[BATCH], evJoin;
    static bool attr_set = false;
    if (!attr_set) {
        cudaFuncSetAttribute(gemm_fused,
            cudaFuncAttributeMaxDynamicSharedMemorySize, GEMM_SMEM_BYTES);
        cudaFuncSetAttribute(flash_tc,
            cudaFuncAttributeMaxDynamicSharedMemorySize, FLASH_SMEM_BYTES);
        cudaStreamCreateWithFlags(&s1, cudaStreamNonBlocking);
        for (int i = 0; i < BATCH; i++)
            cudaEventCreateWithFlags(&evG[i], cudaEventDisableTiming);
        cudaEventCreateWithFlags(&evJoin, cudaEventDisableTiming);
        attr_set = true;
    }
    cudaStream_t s0 = 0;   // this TU's default stream (same one the kernels use)

    // converts on s0
    convert_split_h<<<(MROWS * DMODEL / 4 + 255) / 256, 256, 0, s0>>>(
        (const float4*)X, (uint2*)xh, (uint2*)xl, MROWS * DMODEL / 4);
    convert_w_all<<<(2 * NQK4 + NV4 + 255) / 256, 256, 0, s0>>>(
        (const float4*)Wq, (const float4*)Wk, (const float4*)Wv,
        (uint2*)wq, (uint2*)wk, (uint2*)wv);

    // batch-pipelined: GEMM(b) on s0 ; flash(b) on s1 after GEMM(b)
    for (int b = 0; b < BATCH; b++) {
        gemm_fused<<<dim3(20, 12), 256, GEMM_SMEM_BYTES, s0>>>(
            (const __half*)xh, (const __half*)xl,
            (const __half*)wq, (const __half*)wk, (const __half*)wv,
            (__half*)q, (__half*)kh, (__half*)kl, (__half*)pv, b * 12);
        cudaEventRecord(evG[b], s0);
        cudaStreamWaitEvent(s1, evG[b], 0);
        flash_tc<<<dim3(SEQ / 128, HEADS), 256, FLASH_SMEM_BYTES, s1>>>(
            (const __half*)q, (const __half*)kh, (const __half*)kl,
            (const __half*)pv, out, b);
    }
    // join fork back into s0 (required for capture; also orders completion)
    cudaEventRecord(evJoin, s1);
    cudaStreamWaitEvent(s0, evJoin, 0);
}

// round 12
// speedup vs baseline: 1.1282x; 1.1282x over previous
#include <cuda_runtime.h>
#include <cuda_fp16.h>
#include <cstdint>

#define HEADS   8
#define DK      64
#define DV      192
#define BATCH   4
#define SEQ     1536
#define DMODEL  1536
#define MROWS   (BATCH*SEQ)          // 6144
#define NQK     (HEADS*DK)           // 512
#define NV      (HEADS*DV)           // 1536

// ------------------------- global scratch (no allocs) -----------------------
__device__ __half g_Xh[MROWS * DMODEL], g_Xl[MROWS * DMODEL];   // X hi/lo fp16
__device__ __half g_Wq[DMODEL * NQK];                            // W single fp16
__device__ __half g_Wk[DMODEL * NQK];
__device__ __half g_Wv[DMODEL * NV];
__device__ __half g_Q [MROWS * NQK];                             // Q single fp16 (pre-scaled)
__device__ __half g_Kh[MROWS * NQK], g_Kl[MROWS * NQK];          // K hi/lo fp16
__device__ __half g_V [MROWS * NV];                              // V single fp16

// ------------------------------- helpers ------------------------------------
__device__ __forceinline__ unsigned s2u(const void* p) {
    return (unsigned)__cvta_generic_to_shared(p);
}
__device__ __forceinline__ unsigned packh2(float a, float b) {
    __half ha = __float2half_rn(a), hb = __float2half_rn(b);
    return (unsigned)__half_as_ushort(ha) | ((unsigned)__half_as_ushort(hb) << 16);
}
__device__ __forceinline__ void split2h(float x, float y, unsigned& h, unsigned& l) {
    __half hx = __float2half_rn(x), hy = __float2half_rn(y);
    __half lx = __float2half_rn(x - __half2float(hx));
    __half ly = __float2half_rn(y - __half2float(hy));
    h = (unsigned)__half_as_ushort(hx) | ((unsigned)__half_as_ushort(hy) << 16);
    l = (unsigned)__half_as_ushort(lx) | ((unsigned)__half_as_ushort(ly) << 16);
}
__device__ __forceinline__ void ldm_x4(unsigned* r, unsigned a) {
    asm volatile("ldmatrix.sync.aligned.m8n8.x4.shared.b16 {%0,%1,%2,%3}, [%4];"
        : "=r"(r[0]), "=r"(r[1]), "=r"(r[2]), "=r"(r[3]) : "r"(a));
}
__device__ __forceinline__ void ldm_x4_t(unsigned* r, unsigned a) {
    asm volatile("ldmatrix.sync.aligned.m8n8.x4.trans.shared.b16 {%0,%1,%2,%3}, [%4];"
        : "=r"(r[0]), "=r"(r[1]), "=r"(r[2]), "=r"(r[3]) : "r"(a));
}
__device__ __forceinline__ void mma_f16(float* d, const unsigned* a, const unsigned* b) {
    asm volatile(
        "mma.sync.aligned.m16n8k16.row.col.f32.f16.f16.f32 "
        "{%0,%1,%2,%3}, {%4,%5,%6,%7}, {%8,%9}, {%0,%1,%2,%3};\n"
        : "+f"(d[0]), "+f"(d[1]), "+f"(d[2]), "+f"(d[3])
        : "r"(a[0]), "r"(a[1]), "r"(a[2]), "r"(a[3]), "r"(b[0]), "r"(b[1]));
}
__device__ __forceinline__ void cp16(void* dst, const void* src) {
    unsigned d = s2u(dst);
    asm volatile("cp.async.ca.shared.global [%0], [%1], 16;\n" :: "r"(d), "l"(src));
}
__device__ __forceinline__ void cp_commit() { asm volatile("cp.async.commit_group;\n"); }
__device__ __forceinline__ void cp_wait0()  { asm volatile("cp.async.wait_group 0;\n" ::: "memory"); }
__device__ __forceinline__ void cp_wait1()  { asm volatile("cp.async.wait_group 1;\n" ::: "memory"); }

// --------------------- fp32 -> fp16 hi/lo split (X) --------------------------
__global__ void convert_split_h(const float4* __restrict__ in,
                                uint2* __restrict__ oh, uint2* __restrict__ ol, int n4)
{
    int i = blockIdx.x * blockDim.x + threadIdx.x;
    if (i >= n4) return;
    float4 v = in[i];
    uint2 H, L;
    split2h(v.x, v.y, H.x, L.x);
    split2h(v.z, v.w, H.y, L.y);
    oh[i] = H;  ol[i] = L;
}
// ----------- fp32 -> fp16 single convert, all three W in one launch ----------
#define NQK4 (DMODEL * NQK / 4)   // 196608
#define NV4  (DMODEL * NV / 4)    // 589824
__global__ void convert_w_all(const float4* __restrict__ wq, const float4* __restrict__ wk,
                              const float4* __restrict__ wv,
                              uint2* __restrict__ oq, uint2* __restrict__ ok,
                              uint2* __restrict__ ov)
{
    int i = blockIdx.x * blockDim.x + threadIdx.x;
    const float4* in;  uint2* o;  int j;
    if (i < NQK4)               { in = wq; o = oq; j = i; }
    else if (i < 2 * NQK4)      { in = wk; o = ok; j = i - NQK4; }
    else if (i < 2 * NQK4 + NV4){ in = wv; o = ov; j = i - 2 * NQK4; }
    else return;
    float4 v = in[j];
    uint2 H;
    H.x = packh2(v.x, v.y);
    H.y = packh2(v.z, v.w);
    o[j] = H;
}

// ---------------------------------------------------------------------------
// Fused projection GEMM (fp16): BM=256, BN=128, BK=32, 512 threads (16 warps,
// 8x2 arrangement, warp tile 32x64). Halves W-side L2 traffic vs BM=128.
// Q,K: 2-product (Xh+Xl)@W.  V: 1-product Xh@W.
// Segments by bn: <4 -> Q ; <8 -> K ; else -> V.  cp.async 3-stage, 1 sync/iter.
// Smem/stage (halfs): Ah[256][40] 10240 | Al 10240 | B[32][136] 4352 = 24832
// ---------------------------------------------------------------------------
#define GEMM_STAGE_ELEMS 24832
#define GEMM_SMEM_BYTES  (3 * GEMM_STAGE_ELEMS * 2)   // 148992

__global__ __launch_bounds__(512, 1)
void gemm_fused(const __half* __restrict__ Ahg, const __half* __restrict__ Alg,
                const __half* __restrict__ Wq_, const __half* __restrict__ Wk_,
                const __half* __restrict__ Wv_,
                __half* __restrict__ Q_, __half* __restrict__ Kh_,
                __half* __restrict__ Kl_, __half* __restrict__ V_)
{
    extern __shared__ __half smg[];
    const int tid = threadIdx.x, lane = tid & 31, wid = tid >> 5;
    const int g = lane >> 2, tg = lane & 3;
    const int wm = (wid >> 1) * 32, wn = (wid & 1) * 64;   // wm 0..224
    const int bm = blockIdx.y, bn_g = blockIdx.x;
    const int K = DMODEL;
    const int NT = K >> 5;   // 48

    const __half* Bg;
    int Nb, bnn, seg;
    if (bn_g < 4)      { Bg = Wq_; Nb = NQK; bnn = bn_g;     seg = 0; }
    else if (bn_g < 8) { Bg = Wk_; Nb = NQK; bnn = bn_g - 4; seg = 1; }
    else               { Bg = Wv_; Nb = NV;  bnn = bn_g - 8; seg = 2; }
    const float alpha = (seg == 0) ? 0.125f : 1.0f;
    const bool use_lo = (seg != 2);     // V: single product

    float d[2][8][4];
#pragma unroll
    for (int mt = 0; mt < 2; mt++)
#pragma unroll
        for (int nt = 0; nt < 8; nt++)
#pragma unroll
            for (int i = 0; i < 4; i++) d[mt][nt][i] = 0.f;

    auto issue = [&](int it) {
        __half* s = smg + (it % 3) * GEMM_STAGE_ELEMS;
        int k0 = it * 32;
        // A: 256 rows x 4 chunks of 8 halfs = 1024 chunks (2 x 512 threads)
#pragma unroll
        for (int j = 0; j < 2; j++) {
            int c = tid + j * 512;
            int ar = c >> 2, ac = (c & 3) << 3;
            size_t ga = (size_t)(bm * 256 + ar) * K + k0 + ac;
            cp16(s + ar * 40 + ac, Ahg + ga);
            if (use_lo) cp16(s + 10240 + ar * 40 + ac, Alg + ga);
        }
        // B: 32 rows x 16 chunks — exactly 512
        {
            int br = tid >> 4, bc = (tid & 15) << 3;
            size_t gb = (size_t)(k0 + br) * Nb + bnn * 128 + bc;
            cp16(s + 20480 + br * 136 + bc, Bg + gb);
        }
        cp_commit();
    };

    issue(0);
    issue(1);
    for (int it = 0; it < NT; it++) {
        if (it + 1 < NT) cp_wait1(); else cp_wait0();
        __syncthreads();
        if (it + 2 < NT) issue(it + 2);
        const __half* s = smg + (it % 3) * GEMM_STAGE_ELEMS;

#pragma unroll
        for (int ks = 0; ks < 2; ks++) {
            const int kk = ks * 16;
            unsigned ah[2][4], al[2][4];
            const int arow = lane & 15, acol = kk + ((lane >> 4) << 3);
#pragma unroll
            for (int mt = 0; mt < 2; mt++) {
                ldm_x4(ah[mt], s2u(s + (wm + mt * 16 + arow) * 40 + acol));
                if (use_lo)
                    ldm_x4(al[mt], s2u(s + 10240 + (wm + mt * 16 + arow) * 40 + acol));
            }
            const int krow = kk + (lane & 7) + ((lane >> 3) & 1) * 8;
#pragma unroll
            for (int ntp = 0; ntp < 4; ntp++) {
                const int ncol = wn + ntp * 16 + ((lane >> 4) << 3);
                unsigned bh[4];
                ldm_x4_t(bh, s2u(s + 20480 + krow * 136 + ncol));
#pragma unroll
                for (int mt = 0; mt < 2; mt++) {
                    mma_f16(d[mt][2 * ntp],     ah[mt], bh);
                    mma_f16(d[mt][2 * ntp + 1], ah[mt], bh + 2);
                    if (use_lo) {
                        mma_f16(d[mt][2 * ntp],     al[mt], bh);
                        mma_f16(d[mt][2 * ntp + 1], al[mt], bh + 2);
                    }
                }
            }
        }
    }

    // epilogue (per segment)
#pragma unroll
    for (int mt = 0; mt < 2; mt++) {
        int r0 = bm * 256 + wm + mt * 16 + g;
#pragma unroll
        for (int nt = 0; nt < 8; nt++) {
            int c = bnn * 128 + wn + nt * 8 + 2 * tg;
            float v0 = d[mt][nt][0] * alpha, v1 = d[mt][nt][1] * alpha;
            float v2 = d[mt][nt][2] * alpha, v3 = d[mt][nt][3] * alpha;
            if (seg == 0) {
                *(unsigned*)(Q_ + (size_t)r0 * NQK + c)       = packh2(v0, v1);
                *(unsigned*)(Q_ + (size_t)(r0 + 8) * NQK + c) = packh2(v2, v3);
            } else if (seg == 1) {
                unsigned h01, l01, h23, l23;
                split2h(v0, v1, h01, l01);
                split2h(v2, v3, h23, l23);
                *(unsigned*)(Kh_ + (size_t)r0 * NQK + c)       = h01;
                *(unsigned*)(Kl_ + (size_t)r0 * NQK + c)       = l01;
                *(unsigned*)(Kh_ + (size_t)(r0 + 8) * NQK + c) = h23;
                *(unsigned*)(Kl_ + (size_t)(r0 + 8) * NQK + c) = l23;
            } else {
                *(unsigned*)(V_ + (size_t)r0 * NV + c)       = packh2(v0, v1);
                *(unsigned*)(V_ + (size_t)(r0 + 8) * NV + c) = packh2(v2, v3);
            }
        }
    }
}

// ---------------------------------------------------------------------------
// Flash attention (fp16) — identical to round 9 (bit-identical results).
// Q tile 128 (8 warps x m16), KV tile 64, 3-stage KV, P kept in registers.
// Smem bytes: Qs 18432 | stage x3 44032 = 150528
// ---------------------------------------------------------------------------
#define FLASH_STAGE_BYTES 44032
#define FLASH_SMEM_BYTES  (18432 + 3 * FLASH_STAGE_BYTES)   // 150528

__global__ __launch_bounds__(256, 1)
void flash_tc(const __half* __restrict__ Qg, const __half* __restrict__ Khg,
              const __half* __restrict__ Klg, const __half* __restrict__ V,
              float* __restrict__ out)
{
    extern __shared__ char smc[];
    __half* Qs = (__half*)smc;                     // [128][72]

    const int tid = threadIdx.x, lane = tid & 31, wid = tid >> 5;
    const int g = lane >> 2, tg = lane & 3;
    const int w16 = wid * 16;
    const int b = blockIdx.y >> 3, h = blockIdx.y & 7;
    const int q0 = blockIdx.x * 128;
    const int NT = SEQ / 64;   // 24

#pragma unroll
    for (int r = 0; r < 4; r++) {
        int idx = tid + r * 256;
        int qr = idx >> 3, kc = (idx & 7) << 3;
        *(uint4*)(Qs + qr * 72 + kc) =
            *(const uint4*)(Qg + (size_t)(b * SEQ + q0 + qr) * NQK + h * DK + kc);
    }

    auto issue_kv = [&](int kt) {
        char* st = smc + 18432 + (kt % 3) * FLASH_STAGE_BYTES;
        const int kv0 = kt * 64;
#pragma unroll
        for (int i = 0; i < 2; i++) {
            int idx = tid + i * 256;
            int r = idx >> 3, q = idx & 7;
            size_t go = (size_t)(b * SEQ + kv0 + r) * NQK + h * DK + q * 8;
            cp16(st + r * 144 + q * 16, Khg + go);
            cp16(st + 9216 + r * 144 + q * 16, Klg + go);
        }
#pragma unroll
        for (int i = 0; i < 6; i++) {
            int idx = tid + i * 256;
            int r = idx / 24, cq = idx % 24;
            cp16(st + 18432 + r * 400 + cq * 16,
                 V + (size_t)(b * SEQ + kv0 + r) * NV + h * DV + cq * 8);
        }
        cp_commit();
    };

    issue_kv(0);
    issue_kv(1);
    __syncthreads();

    unsigned qf[4][4];
#pragma unroll
    for (int ks = 0; ks < 4; ks++) {
        const int arow = lane & 15, acol = ks * 16 + ((lane >> 4) << 3);
        ldm_x4(qf[ks], s2u(Qs + (w16 + arow) * 72 + acol));
    }

    float m0 = -1e30f, m1 = -1e30f, l0s = 0.f, l1s = 0.f;
    float o[24][4];
#pragma unroll
    for (int nt = 0; nt < 24; nt++)
#pragma unroll
        for (int i = 0; i < 4; i++) o[nt][i] = 0.f;

    for (int kt = 0; kt < NT; kt++) {
        if (kt + 1 < NT) cp_wait1(); else cp_wait0();
        __syncthreads();
        if (kt + 2 < NT) issue_kv(kt + 2);

        char* st = smc + 18432 + (kt % 3) * FLASH_STAGE_BYTES;
        __half* Kh_s = (__half*)st;
        __half* Kl_s = (__half*)(st + 9216);
        __half* Vs   = (__half*)(st + 18432);

        float s[8][4];
#pragma unroll
        for (int nt = 0; nt < 8; nt++)
#pragma unroll
            for (int i = 0; i < 4; i++) s[nt][i] = 0.f;

#pragma unroll
        for (int ks = 0; ks < 4; ks++) {
            const int kk = ks * 16;
            const int nrow = ((lane >> 4) << 3) + (lane & 7);
            const int kcol = kk + ((lane >> 3) & 1) * 8;
#pragma unroll
            for (int ntp = 0; ntp < 4; ntp++) {
                unsigned kh[4], kl[4];
                ldm_x4(kh, s2u(Kh_s + (ntp * 16 + nrow) * 72 + kcol));
                ldm_x4(kl, s2u(Kl_s + (ntp * 16 + nrow) * 72 + kcol));
                mma_f16(s[2 * ntp],     qf[ks], kh);
                mma_f16(s[2 * ntp],     qf[ks], kl);
                mma_f16(s[2 * ntp + 1], qf[ks], kh + 2);
                mma_f16(s[2 * ntp + 1], qf[ks], kl + 2);
            }
        }

        float mx0 = -1e30f, mx1 = -1e30f;
#pragma unroll
        for (int nt = 0; nt < 8; nt++) {
            mx0 = fmaxf(mx0, fmaxf(s[nt][0], s[nt][1]));
            mx1 = fmaxf(mx1, fmaxf(s[nt][2], s[nt][3]));
        }
        mx0 = fmaxf(mx0, __shfl_xor_sync(0xffffffffu, mx0, 1));
        mx0 = fmaxf(mx0, __shfl_xor_sync(0xffffffffu, mx0, 2));
        mx1 = fmaxf(mx1, __shfl_xor_sync(0xffffffffu, mx1, 1));
        mx1 = fmaxf(mx1, __shfl_xor_sync(0xffffffffu, mx1, 2));

        float nm0 = fmaxf(m0, mx0), nm1 = fmaxf(m1, mx1);
        float a0 = __expf(m0 - nm0), a1 = __expf(m1 - nm1);
        float sum0 = 0.f, sum1 = 0.f;
#pragma unroll
        for (int nt = 0; nt < 8; nt++) {
            s[nt][0] = __expf(s[nt][0] - nm0); sum0 += s[nt][0];
            s[nt][1] = __expf(s[nt][1] - nm0); sum0 += s[nt][1];
            s[nt][2] = __expf(s[nt][2] - nm1); sum1 += s[nt][2];
            s[nt][3] = __expf(s[nt][3] - nm1); sum1 += s[nt][3];
        }
        sum0 += __shfl_xor_sync(0xffffffffu, sum0, 1);
        sum0 += __shfl_xor_sync(0xffffffffu, sum0, 2);
        sum1 += __shfl_xor_sync(0xffffffffu, sum1, 1);
        sum1 += __shfl_xor_sync(0xffffffffu, sum1, 2);
        l0s = l0s * a0 + sum0;  l1s = l1s * a1 + sum1;
        m0 = nm0;  m1 = nm1;

#pragma unroll
        for (int nt = 0; nt < 24; nt++) {
            o[nt][0] *= a0; o[nt][1] *= a0;
            o[nt][2] *= a1; o[nt][3] *= a1;
        }

#pragma unroll
        for (int c = 0; c < 4; c++) {
            unsigned ap[4];
            ap[0] = packh2(s[2 * c][0],     s[2 * c][1]);
            ap[1] = packh2(s[2 * c][2],     s[2 * c][3]);
            ap[2] = packh2(s[2 * c + 1][0], s[2 * c + 1][1]);
            ap[3] = packh2(s[2 * c + 1][2], s[2 * c + 1][3]);
            const int krow = 16 * c + (lane & 7) + ((lane >> 3) & 1) * 8;
#pragma unroll
            for (int ntp = 0; ntp < 12; ntp++) {
                const int ncol = ntp * 16 + ((lane >> 4) << 3);
                unsigned bv[4];
                ldm_x4_t(bv, s2u(Vs + krow * 200 + ncol));
                mma_f16(o[2 * ntp],     ap, bv);
                mma_f16(o[2 * ntp + 1], ap, bv + 2);
            }
        }
    }

    float i0 = 1.f / l0s, i1 = 1.f / l1s;
    int r0 = b * SEQ + q0 + w16 + g, r1 = r0 + 8;
#pragma unroll
    for (int nt = 0; nt < 24; nt++) {
        int c = h * DV + nt * 8 + 2 * tg;
        *(float2*)(out + (size_t)r0 * NV + c) = make_float2(o[nt][0] * i0, o[nt][1] * i0);
        *(float2*)(out + (size_t)r1 * NV + c) = make_float2(o[nt][2] * i1, o[nt][3] * i1);
    }
}

// ---------------------------------------------------------------------------
extern "C" void kernel_launch(void* const* d_in, const int* in_sizes, int n_in,
                              void* d_out, int out_size)
{
    const float* X  = (const float*)d_in[0];
    const float* Wq = (const float*)d_in[1];
    const float* Wk = (const float*)d_in[2];
    const float* Wv = (const float*)d_in[3];
    float* out = (float*)d_out;

    void *xh, *xl, *wq, *wk, *wv, *q, *kh, *kl, *pv;
    cudaGetSymbolAddress(&xh, g_Xh); cudaGetSymbolAddress(&xl, g_Xl);
    cudaGetSymbolAddress(&wq, g_Wq); cudaGetSymbolAddress(&wk, g_Wk);
    cudaGetSymbolAddress(&wv, g_Wv);
    cudaGetSymbolAddress(&q, g_Q);
    cudaGetSymbolAddress(&kh, g_Kh); cudaGetSymbolAddress(&kl, g_Kl);
    cudaGetSymbolAddress(&pv, g_V);

    static bool attr_set = false;
    if (!attr_set) {
        cudaFuncSetAttribute(gemm_fused,
            cudaFuncAttributeMaxDynamicSharedMemorySize, GEMM_SMEM_BYTES);
        cudaFuncSetAttribute(flash_tc,
            cudaFuncAttributeMaxDynamicSharedMemorySize, FLASH_SMEM_BYTES);
        attr_set = true;
    }

    // X -> fp16 hi/lo ; all W -> fp16 single (one launch)
    convert_split_h<<<(MROWS * DMODEL / 4 + 255) / 256, 256>>>(
        (const float4*)X, (uint2*)xh, (uint2*)xl, MROWS * DMODEL / 4);
    convert_w_all<<<(2 * NQK4 + NV4 + 255) / 256, 256>>>(
        (const float4*)Wq, (const float4*)Wk, (const float4*)Wv,
        (uint2*)wq, (uint2*)wk, (uint2*)wv);

    // one fused projection GEMM: Q | K | V  (BM=256 -> grid (20, 24))
    gemm_fused<<<dim3(20, MROWS / 256), 512, GEMM_SMEM_BYTES>>>(
        (const __half*)xh, (const __half*)xl,
        (const __half*)wq, (const __half*)wk, (const __half*)wv,
        (__half*)q, (__half*)kh, (__half*)kl, (__half*)pv);

    flash_tc<<<dim3(SEQ / 128, BATCH * HEADS), 256, FLASH_SMEM_BYTES>>>(
        (const __half*)q, (const __half*)kh, (const __half*)kl,
        (const __half*)pv, out);
}

// round 14
// speedup vs baseline: 1.2382x; 1.0975x over previous
#include <cuda_runtime.h>
#include <cuda_fp16.h>
#include <cstdint>

#define HEADS   8
#define DK      64
#define DV      192
#define BATCH   4
#define SEQ     1536
#define DMODEL  1536
#define MROWS   (BATCH*SEQ)          // 6144
#define NQK     (HEADS*DK)           // 512
#define NV      (HEADS*DV)           // 1536

// ------------------------- global scratch (no allocs) -----------------------
__device__ __half g_Xh[MROWS * DMODEL], g_Xl[MROWS * DMODEL];   // X hi/lo fp16
__device__ __half g_Wq[DMODEL * NQK];                            // W single fp16
__device__ __half g_Wk[DMODEL * NQK];
__device__ __half g_Wv[DMODEL * NV];
__device__ __half g_Q [MROWS * NQK];                             // Q single fp16 (pre-scaled)
__device__ __half g_Kh[MROWS * NQK], g_Kl[MROWS * NQK];          // K hi/lo fp16
__device__ __half g_V [MROWS * NV];                              // V single fp16

// ------------------------------- helpers ------------------------------------
__device__ __forceinline__ unsigned s2u(const void* p) {
    return (unsigned)__cvta_generic_to_shared(p);
}
__device__ __forceinline__ unsigned packh2(float a, float b) {
    __half ha = __float2half_rn(a), hb = __float2half_rn(b);
    return (unsigned)__half_as_ushort(ha) | ((unsigned)__half_as_ushort(hb) << 16);
}
__device__ __forceinline__ void split2h(float x, float y, unsigned& h, unsigned& l) {
    __half hx = __float2half_rn(x), hy = __float2half_rn(y);
    __half lx = __float2half_rn(x - __half2float(hx));
    __half ly = __float2half_rn(y - __half2float(hy));
    h = (unsigned)__half_as_ushort(hx) | ((unsigned)__half_as_ushort(hy) << 16);
    l = (unsigned)__half_as_ushort(lx) | ((unsigned)__half_as_ushort(ly) << 16);
}
__device__ __forceinline__ void ldm_x4(unsigned* r, unsigned a) {
    asm volatile("ldmatrix.sync.aligned.m8n8.x4.shared.b16 {%0,%1,%2,%3}, [%4];"
        : "=r"(r[0]), "=r"(r[1]), "=r"(r[2]), "=r"(r[3]) : "r"(a));
}
__device__ __forceinline__ void ldm_x4_t(unsigned* r, unsigned a) {
    asm volatile("ldmatrix.sync.aligned.m8n8.x4.trans.shared.b16 {%0,%1,%2,%3}, [%4];"
        : "=r"(r[0]), "=r"(r[1]), "=r"(r[2]), "=r"(r[3]) : "r"(a));
}
__device__ __forceinline__ void mma_f16(float* d, const unsigned* a, const unsigned* b) {
    asm volatile(
        "mma.sync.aligned.m16n8k16.row.col.f32.f16.f16.f32 "
        "{%0,%1,%2,%3}, {%4,%5,%6,%7}, {%8,%9}, {%0,%1,%2,%3};\n"
        : "+f"(d[0]), "+f"(d[1]), "+f"(d[2]), "+f"(d[3])
        : "r"(a[0]), "r"(a[1]), "r"(a[2]), "r"(a[3]), "r"(b[0]), "r"(b[1]));
}
__device__ __forceinline__ void cp16(void* dst, const void* src) {
    unsigned d = s2u(dst);
    asm volatile("cp.async.ca.shared.global [%0], [%1], 16;\n" :: "r"(d), "l"(src));
}
__device__ __forceinline__ void cp_commit() { asm volatile("cp.async.commit_group;\n"); }
__device__ __forceinline__ void cp_wait0()  { asm volatile("cp.async.wait_group 0;\n" ::: "memory"); }
__device__ __forceinline__ void cp_wait1()  { asm volatile("cp.async.wait_group 1;\n" ::: "memory"); }

// --------------------- fp32 -> fp16 hi/lo split (X) --------------------------
__global__ void convert_split_h(const float4* __restrict__ in,
                                uint2* __restrict__ oh, uint2* __restrict__ ol, int n4)
{
    int i = blockIdx.x * blockDim.x + threadIdx.x;
    if (i >= n4) return;
    float4 v = in[i];
    uint2 H, L;
    split2h(v.x, v.y, H.x, L.x);
    split2h(v.z, v.w, H.y, L.y);
    oh[i] = H;  ol[i] = L;
}
// ----------- fp32 -> fp16 single convert, all three W in one launch ----------
#define NQK4 (DMODEL * NQK / 4)   // 196608
#define NV4  (DMODEL * NV / 4)    // 589824
__global__ void convert_w_all(const float4* __restrict__ wq, const float4* __restrict__ wk,
                              const float4* __restrict__ wv,
                              uint2* __restrict__ oq, uint2* __restrict__ ok,
                              uint2* __restrict__ ov)
{
    int i = blockIdx.x * blockDim.x + threadIdx.x;
    const float4* in;  uint2* o;  int j;
    if (i < NQK4)               { in = wq; o = oq; j = i; }
    else if (i < 2 * NQK4)      { in = wk; o = ok; j = i - NQK4; }
    else if (i < 2 * NQK4 + NV4){ in = wv; o = ov; j = i - 2 * NQK4; }
    else return;
    float4 v = in[j];
    uint2 H;
    H.x = packh2(v.x, v.y);
    H.y = packh2(v.z, v.w);
    o[j] = H;
}

// ---------------------------------------------------------------------------
// Fused projection GEMM (fp16) — R9 config: BM=128 BN=128 BK=32,
// 256 thr (8 warps 4x2), warp tile 32x64, cp.async 3-stage, 2 CTAs/SM.
// Q,K: 2-product (Xh+Xl)@W.  V: 1-product Xh@W.
// ---------------------------------------------------------------------------
#define GEMM_STAGE_ELEMS 14592
#define GEMM_SMEM_BYTES  (3 * GEMM_STAGE_ELEMS * 2)   // 87552

__global__ __launch_bounds__(256, 2)
void gemm_fused(const __half* __restrict__ Ahg, const __half* __restrict__ Alg,
                const __half* __restrict__ Wq_, const __half* __restrict__ Wk_,
                const __half* __restrict__ Wv_,
                __half* __restrict__ Q_, __half* __restrict__ Kh_,
                __half* __restrict__ Kl_, __half* __restrict__ V_)
{
    extern __shared__ __half smg[];
    const int tid = threadIdx.x, lane = tid & 31, wid = tid >> 5;
    const int g = lane >> 2, tg = lane & 3;
    const int wm = (wid >> 1) * 32, wn = (wid & 1) * 64;
    const int bm = blockIdx.y, bn_g = blockIdx.x;
    const int K = DMODEL;
    const int NT = K >> 5;   // 48

    const __half* Bg;
    int Nb, bnn, seg;
    if (bn_g < 4)      { Bg = Wq_; Nb = NQK; bnn = bn_g;     seg = 0; }
    else if (bn_g < 8) { Bg = Wk_; Nb = NQK; bnn = bn_g - 4; seg = 1; }
    else               { Bg = Wv_; Nb = NV;  bnn = bn_g - 8; seg = 2; }
    const float alpha = (seg == 0) ? 0.125f : 1.0f;
    const bool use_lo = (seg != 2);

    float d[2][8][4];
#pragma unroll
    for (int mt = 0; mt < 2; mt++)
#pragma unroll
        for (int nt = 0; nt < 8; nt++)
#pragma unroll
            for (int i = 0; i < 4; i++) d[mt][nt][i] = 0.f;

    auto issue = [&](int it) {
        __half* s = smg + (it % 3) * GEMM_STAGE_ELEMS;
        int k0 = it * 32;
#pragma unroll
        for (int j = 0; j < 2; j++) {
            int c = tid + j * 256;
            int ar = c >> 2, ac = (c & 3) << 3;
            size_t ga = (size_t)(bm * 128 + ar) * K + k0 + ac;
            cp16(s + ar * 40 + ac, Ahg + ga);
            if (use_lo) cp16(s + 5120 + ar * 40 + ac, Alg + ga);
            int br = c >> 4, bc = (c & 15) << 3;
            size_t gb = (size_t)(k0 + br) * Nb + bnn * 128 + bc;
            cp16(s + 10240 + br * 136 + bc, Bg + gb);
        }
        cp_commit();
    };

    issue(0);
    issue(1);
    for (int it = 0; it < NT; it++) {
        if (it + 1 < NT) cp_wait1(); else cp_wait0();
        __syncthreads();
        if (it + 2 < NT) issue(it + 2);
        const __half* s = smg + (it % 3) * GEMM_STAGE_ELEMS;

#pragma unroll
        for (int ks = 0; ks < 2; ks++) {
            const int kk = ks * 16;
            unsigned ah[2][4], al[2][4];
            const int arow = lane & 15, acol = kk + ((lane >> 4) << 3);
#pragma unroll
            for (int mt = 0; mt < 2; mt++) {
                ldm_x4(ah[mt], s2u(s + (wm + mt * 16 + arow) * 40 + acol));
                if (use_lo)
                    ldm_x4(al[mt], s2u(s + 5120 + (wm + mt * 16 + arow) * 40 + acol));
            }
            const int krow = kk + (lane & 7) + ((lane >> 3) & 1) * 8;
#pragma unroll
            for (int ntp = 0; ntp < 4; ntp++) {
                const int ncol = wn + ntp * 16 + ((lane >> 4) << 3);
                unsigned bh[4];
                ldm_x4_t(bh, s2u(s + 10240 + krow * 136 + ncol));
#pragma unroll
                for (int mt = 0; mt < 2; mt++) {
                    mma_f16(d[mt][2 * ntp],     ah[mt], bh);
                    mma_f16(d[mt][2 * ntp + 1], ah[mt], bh + 2);
                    if (use_lo) {
                        mma_f16(d[mt][2 * ntp],     al[mt], bh);
                        mma_f16(d[mt][2 * ntp + 1], al[mt], bh + 2);
                    }
                }
            }
        }
    }

    // epilogue (per segment)
#pragma unroll
    for (int mt = 0; mt < 2; mt++) {
        int r0 = bm * 128 + wm + mt * 16 + g;
#pragma unroll
        for (int nt = 0; nt < 8; nt++) {
            int c = bnn * 128 + wn + nt * 8 + 2 * tg;
            float v0 = d[mt][nt][0] * alpha, v1 = d[mt][nt][1] * alpha;
            float v2 = d[mt][nt][2] * alpha, v3 = d[mt][nt][3] * alpha;
            if (seg == 0) {
                *(unsigned*)(Q_ + (size_t)r0 * NQK + c)       = packh2(v0, v1);
                *(unsigned*)(Q_ + (size_t)(r0 + 8) * NQK + c) = packh2(v2, v3);
            } else if (seg == 1) {
                unsigned h01, l01, h23, l23;
                split2h(v0, v1, h01, l01);
                split2h(v2, v3, h23, l23);
                *(unsigned*)(Kh_ + (size_t)r0 * NQK + c)       = h01;
                *(unsigned*)(Kl_ + (size_t)r0 * NQK + c)       = l01;
                *(unsigned*)(Kh_ + (size_t)(r0 + 8) * NQK + c) = h23;
                *(unsigned*)(Kl_ + (size_t)(r0 + 8) * NQK + c) = l23;
            } else {
                *(unsigned*)(V_ + (size_t)r0 * NV + c)       = packh2(v0, v1);
                *(unsigned*)(V_ + (size_t)(r0 + 8) * NV + c) = packh2(v2, v3);
            }
        }
    }
}

// ---------------------------------------------------------------------------
// Flash attention (fp16) — R9 kernel + alpha==1 rescale skip (bit-identical).
// Q tile 128 (8 warps x m16), KV tile 64, 3-stage KV, P kept in registers.
// Smem bytes: Qs 18432 | stage x3 44032 = 150528
// ---------------------------------------------------------------------------
#define FLASH_STAGE_BYTES 44032
#define FLASH_SMEM_BYTES  (18432 + 3 * FLASH_STAGE_BYTES)   // 150528

__global__ __launch_bounds__(256, 1)
void flash_tc(const __half* __restrict__ Qg, const __half* __restrict__ Khg,
              const __half* __restrict__ Klg, const __half* __restrict__ V,
              float* __restrict__ out)
{
    extern __shared__ char smc[];
    __half* Qs = (__half*)smc;                     // [128][72]

    const int tid = threadIdx.x, lane = tid & 31, wid = tid >> 5;
    const int g = lane >> 2, tg = lane & 3;
    const int w16 = wid * 16;
    const int b = blockIdx.y >> 3, h = blockIdx.y & 7;
    const int q0 = blockIdx.x * 128;
    const int NT = SEQ / 64;   // 24

#pragma unroll
    for (int r = 0; r < 4; r++) {
        int idx = tid + r * 256;
        int qr = idx >> 3, kc = (idx & 7) << 3;
        *(uint4*)(Qs + qr * 72 + kc) =
            *(const uint4*)(Qg + (size_t)(b * SEQ + q0 + qr) * NQK + h * DK + kc);
    }

    auto issue_kv = [&](int kt) {
        char* st = smc + 18432 + (kt % 3) * FLASH_STAGE_BYTES;
        const int kv0 = kt * 64;
#pragma unroll
        for (int i = 0; i < 2; i++) {
            int idx = tid + i * 256;
            int r = idx >> 3, q = idx & 7;
            size_t go = (size_t)(b * SEQ + kv0 + r) * NQK + h * DK + q * 8;
            cp16(st + r * 144 + q * 16, Khg + go);
            cp16(st + 9216 + r * 144 + q * 16, Klg + go);
        }
#pragma unroll
        for (int i = 0; i < 6; i++) {
            int idx = tid + i * 256;
            int r = idx / 24, cq = idx % 24;
            cp16(st + 18432 + r * 400 + cq * 16,
                 V + (size_t)(b * SEQ + kv0 + r) * NV + h * DV + cq * 8);
        }
        cp_commit();
    };

    issue_kv(0);
    issue_kv(1);
    __syncthreads();

    unsigned qf[4][4];
#pragma unroll
    for (int ks = 0; ks < 4; ks++) {
        const int arow = lane & 15, acol = ks * 16 + ((lane >> 4) << 3);
        ldm_x4(qf[ks], s2u(Qs + (w16 + arow) * 72 + acol));
    }

    float m0 = -1e30f, m1 = -1e30f, l0s = 0.f, l1s = 0.f;
    float o[24][4];
#pragma unroll
    for (int nt = 0; nt < 24; nt++)
#pragma unroll
        for (int i = 0; i < 4; i++) o[nt][i] = 0.f;

    for (int kt = 0; kt < NT; kt++) {
        if (kt + 1 < NT) cp_wait1(); else cp_wait0();
        __syncthreads();
        if (kt + 2 < NT) issue_kv(kt + 2);

        char* st = smc + 18432 + (kt % 3) * FLASH_STAGE_BYTES;
        __half* Kh_s = (__half*)st;
        __half* Kl_s = (__half*)(st + 9216);
        __half* Vs   = (__half*)(st + 18432);

        float s[8][4];
#pragma unroll
        for (int nt = 0; nt < 8; nt++)
#pragma unroll
            for (int i = 0; i < 4; i++) s[nt][i] = 0.f;

#pragma unroll
        for (int ks = 0; ks < 4; ks++) {
            const int kk = ks * 16;
            const int nrow = ((lane >> 4) << 3) + (lane & 7);
            const int kcol = kk + ((lane >> 3) & 1) * 8;
#pragma unroll
            for (int ntp = 0; ntp < 4; ntp++) {
                unsigned kh[4], kl[4];
                ldm_x4(kh, s2u(Kh_s + (ntp * 16 + nrow) * 72 + kcol));
                ldm_x4(kl, s2u(Kl_s + (ntp * 16 + nrow) * 72 + kcol));
                mma_f16(s[2 * ntp],     qf[ks], kh);
                mma_f16(s[2 * ntp],     qf[ks], kl);
                mma_f16(s[2 * ntp + 1], qf[ks], kh + 2);
                mma_f16(s[2 * ntp + 1], qf[ks], kl + 2);
            }
        }

        float mx0 = -1e30f, mx1 = -1e30f;
#pragma unroll
        for (int nt = 0; nt < 8; nt++) {
            mx0 = fmaxf(mx0, fmaxf(s[nt][0], s[nt][1]));
            mx1 = fmaxf(mx1, fmaxf(s[nt][2], s[nt][3]));
        }
        mx0 = fmaxf(mx0, __shfl_xor_sync(0xffffffffu, mx0, 1));
        mx0 = fmaxf(mx0, __shfl_xor_sync(0xffffffffu, mx0, 2));
        mx1 = fmaxf(mx1, __shfl_xor_sync(0xffffffffu, mx1, 1));
        mx1 = fmaxf(mx1, __shfl_xor_sync(0xffffffffu, mx1, 2));

        float nm0 = fmaxf(m0, mx0), nm1 = fmaxf(m1, mx1);
        float a0 = __expf(m0 - nm0), a1 = __expf(m1 - nm1);
        float sum0 = 0.f, sum1 = 0.f;
#pragma unroll
        for (int nt = 0; nt < 8; nt++) {
            s[nt][0] = __expf(s[nt][0] - nm0); sum0 += s[nt][0];
            s[nt][1] = __expf(s[nt][1] - nm0); sum0 += s[nt][1];
            s[nt][2] = __expf(s[nt][2] - nm1); sum1 += s[nt][2];
            s[nt][3] = __expf(s[nt][3] - nm1); sum1 += s[nt][3];
        }
        sum0 += __shfl_xor_sync(0xffffffffu, sum0, 1);
        sum0 += __shfl_xor_sync(0xffffffffu, sum0, 2);
        sum1 += __shfl_xor_sync(0xffffffffu, sum1, 1);
        sum1 += __shfl_xor_sync(0xffffffffu, sum1, 2);
        l0s = l0s * a0 + sum0;  l1s = l1s * a1 + sum1;
        m0 = nm0;  m1 = nm1;

        // rescale only when the running max actually changed.
        // multiplying by exactly 1.0f is an fp32 identity -> bit-identical.
        if (!(a0 == 1.f && a1 == 1.f)) {
#pragma unroll
            for (int nt = 0; nt < 24; nt++) {
                o[nt][0] *= a0; o[nt][1] *= a0;
                o[nt][2] *= a1; o[nt][3] *= a1;
            }
        }

#pragma unroll
        for (int c = 0; c < 4; c++) {
            unsigned ap[4];
            ap[0] = packh2(s[2 * c][0],     s[2 * c][1]);
            ap[1] = packh2(s[2 * c][2],     s[2 * c][3]);
            ap[2] = packh2(s[2 * c + 1][0], s[2 * c + 1][1]);
            ap[3] = packh2(s[2 * c + 1][2], s[2 * c + 1][3]);
            const int krow = 16 * c + (lane & 7) + ((lane >> 3) & 1) * 8;
#pragma unroll
            for (int ntp = 0; ntp < 12; ntp++) {
                const int ncol = ntp * 16 + ((lane >> 4) << 3);
                unsigned bv[4];
                ldm_x4_t(bv, s2u(Vs + krow * 200 + ncol));
                mma_f16(o[2 * ntp],     ap, bv);
                mma_f16(o[2 * ntp + 1], ap, bv + 2);
            }
        }
    }

    float i0 = 1.f / l0s, i1 = 1.f / l1s;
    int r0 = b * SEQ + q0 + w16 + g, r1 = r0 + 8;
#pragma unroll
    for (int nt = 0; nt < 24; nt++) {
        int c = h * DV + nt * 8 + 2 * tg;
        *(float2*)(out + (size_t)r0 * NV + c) = make_float2(o[nt][0] * i0, o[nt][1] * i0);
        *(float2*)(out + (size_t)r1 * NV + c) = make_float2(o[nt][2] * i1, o[nt][3] * i1);
    }
}

// ---------------------------------------------------------------------------
extern "C" void kernel_launch(void* const* d_in, const int* in_sizes, int n_in,
                              void* d_out, int out_size)
{
    const float* X  = (const float*)d_in[0];
    const float* Wq = (const float*)d_in[1];
    const float* Wk = (const float*)d_in[2];
    const float* Wv = (const float*)d_in[3];
    float* out = (float*)d_out;

    void *xh, *xl, *wq, *wk, *wv, *q, *kh, *kl, *pv;
    cudaGetSymbolAddress(&xh, g_Xh); cudaGetSymbolAddress(&xl, g_Xl);
    cudaGetSymbolAddress(&wq, g_Wq); cudaGetSymbolAddress(&wk, g_Wk);
    cudaGetSymbolAddress(&wv, g_Wv);
    cudaGetSymbolAddress(&q, g_Q);
    cudaGetSymbolAddress(&kh, g_Kh); cudaGetSymbolAddress(&kl, g_Kl);
    cudaGetSymbolAddress(&pv, g_V);

    static bool attr_set = false;
    if (!attr_set) {
        cudaFuncSetAttribute(gemm_fused,
            cudaFuncAttributeMaxDynamicSharedMemorySize, GEMM_SMEM_BYTES);
        cudaFuncSetAttribute(flash_tc,
            cudaFuncAttributeMaxDynamicSharedMemorySize, FLASH_SMEM_BYTES);
        attr_set = true;
    }

    // X -> fp16 hi/lo ; all W -> fp16 single (one launch)
    convert_split_h<<<(MROWS * DMODEL / 4 + 255) / 256, 256>>>(
        (const float4*)X, (uint2*)xh, (uint2*)xl, MROWS * DMODEL / 4);
    convert_w_all<<<(2 * NQK4 + NV4 + 255) / 256, 256>>>(
        (const float4*)Wq, (const float4*)Wk, (const float4*)Wv,
        (uint2*)wq, (uint2*)wk, (uint2*)wv);

    // one fused projection GEMM: Q | K | V
    gemm_fused<<<dim3(20, MROWS / 128), 256, GEMM_SMEM_BYTES>>>(
        (const __half*)xh, (const __half*)xl,
        (const __half*)wq, (const __half*)wk, (const __half*)wv,
        (__half*)q, (__half*)kh, (__half*)kl, (__half*)pv);

    flash_tc<<<dim3(SEQ / 128, BATCH * HEADS), 256, FLASH_SMEM_BYTES>>>(
        (const __half*)q, (const __half*)kh, (const __half*)kl,
        (const __half*)pv, out);
}

// round 15
// speedup vs baseline: 1.2984x; 1.0486x over previous
#include <cuda_runtime.h>
#include <cuda_fp16.h>
#include <cstdint>

#define HEADS   8
#define DK      64
#define DV      192
#define BATCH   4
#define SEQ     1536
#define DMODEL  1536
#define MROWS   (BATCH*SEQ)          // 6144
#define NQK     (HEADS*DK)           // 512
#define NV      (HEADS*DV)           // 1536

// ------------------------- global scratch (no allocs) -----------------------
__device__ __half g_Xh[MROWS * DMODEL], g_Xl[MROWS * DMODEL];   // X hi/lo fp16
__device__ __half g_Wq[DMODEL * NQK];                            // W single fp16
__device__ __half g_Wk[DMODEL * NQK];
__device__ __half g_Wv[DMODEL * NV];
__device__ __half g_Q [MROWS * NQK];                             // Q single fp16 (pre-scaled)
__device__ __half g_Kh[MROWS * NQK], g_Kl[MROWS * NQK];          // K hi/lo fp16
__device__ __half g_V [MROWS * NV];                              // V single fp16

// ------------------------------- helpers ------------------------------------
__device__ __forceinline__ unsigned s2u(const void* p) {
    return (unsigned)__cvta_generic_to_shared(p);
}
__device__ __forceinline__ unsigned packh2(float a, float b) {
    __half ha = __float2half_rn(a), hb = __float2half_rn(b);
    return (unsigned)__half_as_ushort(ha) | ((unsigned)__half_as_ushort(hb) << 16);
}
__device__ __forceinline__ void split2h(float x, float y, unsigned& h, unsigned& l) {
    __half hx = __float2half_rn(x), hy = __float2half_rn(y);
    __half lx = __float2half_rn(x - __half2float(hx));
    __half ly = __float2half_rn(y - __half2float(hy));
    h = (unsigned)__half_as_ushort(hx) | ((unsigned)__half_as_ushort(hy) << 16);
    l = (unsigned)__half_as_ushort(lx) | ((unsigned)__half_as_ushort(ly) << 16);
}
__device__ __forceinline__ void ldm_x4(unsigned* r, unsigned a) {
    asm volatile("ldmatrix.sync.aligned.m8n8.x4.shared.b16 {%0,%1,%2,%3}, [%4];"
        : "=r"(r[0]), "=r"(r[1]), "=r"(r[2]), "=r"(r[3]) : "r"(a));
}
__device__ __forceinline__ void ldm_x4_t(unsigned* r, unsigned a) {
    asm volatile("ldmatrix.sync.aligned.m8n8.x4.trans.shared.b16 {%0,%1,%2,%3}, [%4];"
        : "=r"(r[0]), "=r"(r[1]), "=r"(r[2]), "=r"(r[3]) : "r"(a));
}
__device__ __forceinline__ void mma_f16(float* d, const unsigned* a, const unsigned* b) {
    asm volatile(
        "mma.sync.aligned.m16n8k16.row.col.f32.f16.f16.f32 "
        "{%0,%1,%2,%3}, {%4,%5,%6,%7}, {%8,%9}, {%0,%1,%2,%3};\n"
        : "+f"(d[0]), "+f"(d[1]), "+f"(d[2]), "+f"(d[3])
        : "r"(a[0]), "r"(a[1]), "r"(a[2]), "r"(a[3]), "r"(b[0]), "r"(b[1]));
}
__device__ __forceinline__ void cp16(void* dst, const void* src) {
    unsigned d = s2u(dst);
    asm volatile("cp.async.ca.shared.global [%0], [%1], 16;\n" :: "r"(d), "l"(src));
}
__device__ __forceinline__ void cp_commit() { asm volatile("cp.async.commit_group;\n"); }
__device__ __forceinline__ void cp_wait0()  { asm volatile("cp.async.wait_group 0;\n" ::: "memory"); }
__device__ __forceinline__ void cp_wait1()  { asm volatile("cp.async.wait_group 1;\n" ::: "memory"); }

// ---------- single merged convert: X -> fp16 hi/lo ; W -> fp16 single --------
#define NX4  (MROWS * DMODEL / 4)   // 2359296
#define NQK4 (DMODEL * NQK / 4)     // 196608
#define NV4  (DMODEL * NV / 4)      // 589824
#define NALL (NX4 + 2 * NQK4 + NV4)

__global__ void convert_all(const float4* __restrict__ X,
                            const float4* __restrict__ wq, const float4* __restrict__ wk,
                            const float4* __restrict__ wv,
                            uint2* __restrict__ xh, uint2* __restrict__ xl,
                            uint2* __restrict__ oq, uint2* __restrict__ ok,
                            uint2* __restrict__ ov)
{
    int i = blockIdx.x * blockDim.x + threadIdx.x;
    if (i < NX4) {
        float4 v = X[i];
        uint2 H, L;
        split2h(v.x, v.y, H.x, L.x);
        split2h(v.z, v.w, H.y, L.y);
        xh[i] = H;  xl[i] = L;
        return;
    }
    i -= NX4;
    const float4* in;  uint2* o;  int j;
    if (i < NQK4)                { in = wq; o = oq; j = i; }
    else if (i < 2 * NQK4)       { in = wk; o = ok; j = i - NQK4; }
    else if (i < 2 * NQK4 + NV4) { in = wv; o = ov; j = i - 2 * NQK4; }
    else return;
    float4 v = in[j];
    uint2 H;
    H.x = packh2(v.x, v.y);
    H.y = packh2(v.z, v.w);
    o[j] = H;
}

// ---------------------------------------------------------------------------
// Fused projection GEMM (fp16) — R9 config: BM=128 BN=128 BK=32,
// 256 thr (8 warps 4x2), warp tile 32x64, cp.async 3-stage, 2 CTAs/SM.
// Q,K: 2-product (Xh+Xl)@W.  V: 1-product Xh@W.
// ---------------------------------------------------------------------------
#define GEMM_STAGE_ELEMS 14592
#define GEMM_SMEM_BYTES  (3 * GEMM_STAGE_ELEMS * 2)   // 87552

__global__ __launch_bounds__(256, 2)
void gemm_fused(const __half* __restrict__ Ahg, const __half* __restrict__ Alg,
                const __half* __restrict__ Wq_, const __half* __restrict__ Wk_,
                const __half* __restrict__ Wv_,
                __half* __restrict__ Q_, __half* __restrict__ Kh_,
                __half* __restrict__ Kl_, __half* __restrict__ V_)
{
    extern __shared__ __half smg[];
    const int tid = threadIdx.x, lane = tid & 31, wid = tid >> 5;
    const int g = lane >> 2, tg = lane & 3;
    const int wm = (wid >> 1) * 32, wn = (wid & 1) * 64;
    const int bm = blockIdx.y, bn_g = blockIdx.x;
    const int K = DMODEL;
    const int NT = K >> 5;   // 48

    const __half* Bg;
    int Nb, bnn, seg;
    if (bn_g < 4)      { Bg = Wq_; Nb = NQK; bnn = bn_g;     seg = 0; }
    else if (bn_g < 8) { Bg = Wk_; Nb = NQK; bnn = bn_g - 4; seg = 1; }
    else               { Bg = Wv_; Nb = NV;  bnn = bn_g - 8; seg = 2; }
    const float alpha = (seg == 0) ? 0.125f : 1.0f;
    const bool use_lo = (seg != 2);

    float d[2][8][4];
#pragma unroll
    for (int mt = 0; mt < 2; mt++)
#pragma unroll
        for (int nt = 0; nt < 8; nt++)
#pragma unroll
            for (int i = 0; i < 4; i++) d[mt][nt][i] = 0.f;

    auto issue = [&](int it) {
        __half* s = smg + (it % 3) * GEMM_STAGE_ELEMS;
        int k0 = it * 32;
#pragma unroll
        for (int j = 0; j < 2; j++) {
            int c = tid + j * 256;
            int ar = c >> 2, ac = (c & 3) << 3;
            size_t ga = (size_t)(bm * 128 + ar) * K + k0 + ac;
            cp16(s + ar * 40 + ac, Ahg + ga);
            if (use_lo) cp16(s + 5120 + ar * 40 + ac, Alg + ga);
            int br = c >> 4, bc = (c & 15) << 3;
            size_t gb = (size_t)(k0 + br) * Nb + bnn * 128 + bc;
            cp16(s + 10240 + br * 136 + bc, Bg + gb);
        }
        cp_commit();
    };

    issue(0);
    issue(1);
    for (int it = 0; it < NT; it++) {
        if (it + 1 < NT) cp_wait1(); else cp_wait0();
        __syncthreads();
        if (it + 2 < NT) issue(it + 2);
        const __half* s = smg + (it % 3) * GEMM_STAGE_ELEMS;

#pragma unroll
        for (int ks = 0; ks < 2; ks++) {
            const int kk = ks * 16;
            unsigned ah[2][4], al[2][4];
            const int arow = lane & 15, acol = kk + ((lane >> 4) << 3);
#pragma unroll
            for (int mt = 0; mt < 2; mt++) {
                ldm_x4(ah[mt], s2u(s + (wm + mt * 16 + arow) * 40 + acol));
                if (use_lo)
                    ldm_x4(al[mt], s2u(s + 5120 + (wm + mt * 16 + arow) * 40 + acol));
            }
            const int krow = kk + (lane & 7) + ((lane >> 3) & 1) * 8;
#pragma unroll
            for (int ntp = 0; ntp < 4; ntp++) {
                const int ncol = wn + ntp * 16 + ((lane >> 4) << 3);
                unsigned bh[4];
                ldm_x4_t(bh, s2u(s + 10240 + krow * 136 + ncol));
#pragma unroll
                for (int mt = 0; mt < 2; mt++) {
                    mma_f16(d[mt][2 * ntp],     ah[mt], bh);
                    mma_f16(d[mt][2 * ntp + 1], ah[mt], bh + 2);
                    if (use_lo) {
                        mma_f16(d[mt][2 * ntp],     al[mt], bh);
                        mma_f16(d[mt][2 * ntp + 1], al[mt], bh + 2);
                    }
                }
            }
        }
    }

    // epilogue (per segment)
#pragma unroll
    for (int mt = 0; mt < 2; mt++) {
        int r0 = bm * 128 + wm + mt * 16 + g;
#pragma unroll
        for (int nt = 0; nt < 8; nt++) {
            int c = bnn * 128 + wn + nt * 8 + 2 * tg;
            float v0 = d[mt][nt][0] * alpha, v1 = d[mt][nt][1] * alpha;
            float v2 = d[mt][nt][2] * alpha, v3 = d[mt][nt][3] * alpha;
            if (seg == 0) {
                *(unsigned*)(Q_ + (size_t)r0 * NQK + c)       = packh2(v0, v1);
                *(unsigned*)(Q_ + (size_t)(r0 + 8) * NQK + c) = packh2(v2, v3);
            } else if (seg == 1) {
                unsigned h01, l01, h23, l23;
                split2h(v0, v1, h01, l01);
                split2h(v2, v3, h23, l23);
                *(unsigned*)(Kh_ + (size_t)r0 * NQK + c)       = h01;
                *(unsigned*)(Kl_ + (size_t)r0 * NQK + c)       = l01;
                *(unsigned*)(Kh_ + (size_t)(r0 + 8) * NQK + c) = h23;
                *(unsigned*)(Kl_ + (size_t)(r0 + 8) * NQK + c) = l23;
            } else {
                *(unsigned*)(V_ + (size_t)r0 * NV + c)       = packh2(v0, v1);
                *(unsigned*)(V_ + (size_t)(r0 + 8) * NV + c) = packh2(v2, v3);
            }
        }
    }
}

// ---------------------------------------------------------------------------
// Flash attention (fp16) — EXACT R9 kernel (unconditional rescale).
// Q tile 128 (8 warps x m16), KV tile 64, 3-stage KV, P kept in registers.
// Smem bytes: Qs 18432 | stage x3 44032 = 150528
// ---------------------------------------------------------------------------
#define FLASH_STAGE_BYTES 44032
#define FLASH_SMEM_BYTES  (18432 + 3 * FLASH_STAGE_BYTES)   // 150528

__global__ __launch_bounds__(256, 1)
void flash_tc(const __half* __restrict__ Qg, const __half* __restrict__ Khg,
              const __half* __restrict__ Klg, const __half* __restrict__ V,
              float* __restrict__ out)
{
    extern __shared__ char smc[];
    __half* Qs = (__half*)smc;                     // [128][72]

    const int tid = threadIdx.x, lane = tid & 31, wid = tid >> 5;
    const int g = lane >> 2, tg = lane & 3;
    const int w16 = wid * 16;
    const int b = blockIdx.y >> 3, h = blockIdx.y & 7;
    const int q0 = blockIdx.x * 128;
    const int NT = SEQ / 64;   // 24

#pragma unroll
    for (int r = 0; r < 4; r++) {
        int idx = tid + r * 256;
        int qr = idx >> 3, kc = (idx & 7) << 3;
        *(uint4*)(Qs + qr * 72 + kc) =
            *(const uint4*)(Qg + (size_t)(b * SEQ + q0 + qr) * NQK + h * DK + kc);
    }

    auto issue_kv = [&](int kt) {
        char* st = smc + 18432 + (kt % 3) * FLASH_STAGE_BYTES;
        const int kv0 = kt * 64;
#pragma unroll
        for (int i = 0; i < 2; i++) {
            int idx = tid + i * 256;
            int r = idx >> 3, q = idx & 7;
            size_t go = (size_t)(b * SEQ + kv0 + r) * NQK + h * DK + q * 8;
            cp16(st + r * 144 + q * 16, Khg + go);
            cp16(st + 9216 + r * 144 + q * 16, Klg + go);
        }
#pragma unroll
        for (int i = 0; i < 6; i++) {
            int idx = tid + i * 256;
            int r = idx / 24, cq = idx % 24;
            cp16(st + 18432 + r * 400 + cq * 16,
                 V + (size_t)(b * SEQ + kv0 + r) * NV + h * DV + cq * 8);
        }
        cp_commit();
    };

    issue_kv(0);
    issue_kv(1);
    __syncthreads();

    unsigned qf[4][4];
#pragma unroll
    for (int ks = 0; ks < 4; ks++) {
        const int arow = lane & 15, acol = ks * 16 + ((lane >> 4) << 3);
        ldm_x4(qf[ks], s2u(Qs + (w16 + arow) * 72 + acol));
    }

    float m0 = -1e30f, m1 = -1e30f, l0s = 0.f, l1s = 0.f;
    float o[24][4];
#pragma unroll
    for (int nt = 0; nt < 24; nt++)
#pragma unroll
        for (int i = 0; i < 4; i++) o[nt][i] = 0.f;

    for (int kt = 0; kt < NT; kt++) {
        if (kt + 1 < NT) cp_wait1(); else cp_wait0();
        __syncthreads();
        if (kt + 2 < NT) issue_kv(kt + 2);

        char* st = smc + 18432 + (kt % 3) * FLASH_STAGE_BYTES;
        __half* Kh_s = (__half*)st;
        __half* Kl_s = (__half*)(st + 9216);
        __half* Vs   = (__half*)(st + 18432);

        float s[8][4];
#pragma unroll
        for (int nt = 0; nt < 8; nt++)
#pragma unroll
            for (int i = 0; i < 4; i++) s[nt][i] = 0.f;

#pragma unroll
        for (int ks = 0; ks < 4; ks++) {
            const int kk = ks * 16;
            const int nrow = ((lane >> 4) << 3) + (lane & 7);
            const int kcol = kk + ((lane >> 3) & 1) * 8;
#pragma unroll
            for (int ntp = 0; ntp < 4; ntp++) {
                unsigned kh[4], kl[4];
                ldm_x4(kh, s2u(Kh_s + (ntp * 16 + nrow) * 72 + kcol));
                ldm_x4(kl, s2u(Kl_s + (ntp * 16 + nrow) * 72 + kcol));
                mma_f16(s[2 * ntp],     qf[ks], kh);
                mma_f16(s[2 * ntp],     qf[ks], kl);
                mma_f16(s[2 * ntp + 1], qf[ks], kh + 2);
                mma_f16(s[2 * ntp + 1], qf[ks], kl + 2);
            }
        }

        float mx0 = -1e30f, mx1 = -1e30f;
#pragma unroll
        for (int nt = 0; nt < 8; nt++) {
            mx0 = fmaxf(mx0, fmaxf(s[nt][0], s[nt][1]));
            mx1 = fmaxf(mx1, fmaxf(s[nt][2], s[nt][3]));
        }
        mx0 = fmaxf(mx0, __shfl_xor_sync(0xffffffffu, mx0, 1));
        mx0 = fmaxf(mx0, __shfl_xor_sync(0xffffffffu, mx0, 2));
        mx1 = fmaxf(mx1, __shfl_xor_sync(0xffffffffu, mx1, 1));
        mx1 = fmaxf(mx1, __shfl_xor_sync(0xffffffffu, mx1, 2));

        float nm0 = fmaxf(m0, mx0), nm1 = fmaxf(m1, mx1);
        float a0 = __expf(m0 - nm0), a1 = __expf(m1 - nm1);
        float sum0 = 0.f, sum1 = 0.f;
#pragma unroll
        for (int nt = 0; nt < 8; nt++) {
            s[nt][0] = __expf(s[nt][0] - nm0); sum0 += s[nt][0];
            s[nt][1] = __expf(s[nt][1] - nm0); sum0 += s[nt][1];
            s[nt][2] = __expf(s[nt][2] - nm1); sum1 += s[nt][2];
            s[nt][3] = __expf(s[nt][3] - nm1); sum1 += s[nt][3];
        }
        sum0 += __shfl_xor_sync(0xffffffffu, sum0, 1);
        sum0 += __shfl_xor_sync(0xffffffffu, sum0, 2);
        sum1 += __shfl_xor_sync(0xffffffffu, sum1, 1);
        sum1 += __shfl_xor_sync(0xffffffffu, sum1, 2);
        l0s = l0s * a0 + sum0;  l1s = l1s * a1 + sum1;
        m0 = nm0;  m1 = nm1;

#pragma unroll
        for (int nt = 0; nt < 24; nt++) {
            o[nt][0] *= a0; o[nt][1] *= a0;
            o[nt][2] *= a1; o[nt][3] *= a1;
        }

#pragma unroll
        for (int c = 0; c < 4; c++) {
            unsigned ap[4];
            ap[0] = packh2(s[2 * c][0],     s[2 * c][1]);
            ap[1] = packh2(s[2 * c][2],     s[2 * c][3]);
            ap[2] = packh2(s[2 * c + 1][0], s[2 * c + 1][1]);
            ap[3] = packh2(s[2 * c + 1][2], s[2 * c + 1][3]);
            const int krow = 16 * c + (lane & 7) + ((lane >> 3) & 1) * 8;
#pragma unroll
            for (int ntp = 0; ntp < 12; ntp++) {
                const int ncol = ntp * 16 + ((lane >> 4) << 3);
                unsigned bv[4];
                ldm_x4_t(bv, s2u(Vs + krow * 200 + ncol));
                mma_f16(o[2 * ntp],     ap, bv);
                mma_f16(o[2 * ntp + 1], ap, bv + 2);
            }
        }
    }

    float i0 = 1.f / l0s, i1 = 1.f / l1s;
    int r0 = b * SEQ + q0 + w16 + g, r1 = r0 + 8;
#pragma unroll
    for (int nt = 0; nt < 24; nt++) {
        int c = h * DV + nt * 8 + 2 * tg;
        *(float2*)(out + (size_t)r0 * NV + c) = make_float2(o[nt][0] * i0, o[nt][1] * i0);
        *(float2*)(out + (size_t)r1 * NV + c) = make_float2(o[nt][2] * i1, o[nt][3] * i1);
    }
}

// ---------------------------------------------------------------------------
extern "C" void kernel_launch(void* const* d_in, const int* in_sizes, int n_in,
                              void* d_out, int out_size)
{
    const float* X  = (const float*)d_in[0];
    const float* Wq = (const float*)d_in[1];
    const float* Wk = (const float*)d_in[2];
    const float* Wv = (const float*)d_in[3];
    float* out = (float*)d_out;

    void *xh, *xl, *wq, *wk, *wv, *q, *kh, *kl, *pv;
    cudaGetSymbolAddress(&xh, g_Xh); cudaGetSymbolAddress(&xl, g_Xl);
    cudaGetSymbolAddress(&wq, g_Wq); cudaGetSymbolAddress(&wk, g_Wk);
    cudaGetSymbolAddress(&wv, g_Wv);
    cudaGetSymbolAddress(&q, g_Q);
    cudaGetSymbolAddress(&kh, g_Kh); cudaGetSymbolAddress(&kl, g_Kl);
    cudaGetSymbolAddress(&pv, g_V);

    static bool attr_set = false;
    if (!attr_set) {
        cudaFuncSetAttribute(gemm_fused,
            cudaFuncAttributeMaxDynamicSharedMemorySize, GEMM_SMEM_BYTES);
        cudaFuncSetAttribute(flash_tc,
            cudaFuncAttributeMaxDynamicSharedMemorySize, FLASH_SMEM_BYTES);
        attr_set = true;
    }

    // single merged convert launch: X hi/lo split + all W fp16
    convert_all<<<(NALL + 255) / 256, 256>>>(
        (const float4*)X, (const float4*)Wq, (const float4*)Wk, (const float4*)Wv,
        (uint2*)xh, (uint2*)xl, (uint2*)wq, (uint2*)wk, (uint2*)wv);

    // one fused projection GEMM: Q | K | V
    gemm_fused<<<dim3(20, MROWS / 128), 256, GEMM_SMEM_BYTES>>>(
        (const __half*)xh, (const __half*)xl,
        (const __half*)wq, (const __half*)wk, (const __half*)wv,
        (__half*)q, (__half*)kh, (__half*)kl, (__half*)pv);

    flash_tc<<<dim3(SEQ / 128, BATCH * HEADS), 256, FLASH_SMEM_BYTES>>>(
        (const __half*)q, (const __half*)kh, (const __half*)kl,
        (const __half*)pv, out);
}